// round 13
// baseline (speedup 1.0000x reference)
#include <cuda_runtime.h>
#include <cuda_fp16.h>
#include <cstdint>

#define N_NODES 40000
#define N_EDGES 640000
#define N_GRAPHS 64
#define D 128
#define LN_EPS 1e-5f
#define SCAN_BLK 1024
#define N_SCAN_BLKS ((N_NODES + SCAN_BLK - 1) / SCAN_BLK)   // 40
#define E_QUARTER (N_EDGES / 4)                             // 160000

// ---------------- scratch (no allocations allowed) ----------------
__device__ __half g_h[(size_t)N_NODES * D];
__device__ __half g_agg[(size_t)N_NODES * D];
__device__ __half g_w[7 * D * D];     // 0: fc_w, 1-3: Wl, 4-6: Wr (fp16)
__device__ int g_cnt[N_NODES];
__device__ int g_fill[N_NODES];
__device__ int g_scan[N_NODES];
__device__ int g_bsum[N_SCAN_BLKS];
__device__ int g_rowptr[N_NODES + 1];
__device__ int g_col[N_EDGES];

// ================= helpers =================
__device__ __forceinline__ uint32_t smem_u32(const void* p) {
    uint32_t a;
    asm("{ .reg .u64 t; cvta.to.shared.u64 t, %1; cvt.u32.u64 %0, t; }"
        : "=r"(a) : "l"(p));
    return a;
}
// pack (lo, hi) floats -> f16x2 (lo in low half)
__device__ __forceinline__ uint32_t cvt_f16x2(float lo, float hi) {
    uint32_t r;
    asm("cvt.rn.f16x2.f32 %0, %1, %2;" : "=r"(r) : "f"(hi), "f"(lo));
    return r;
}
__device__ __forceinline__ void ldmx4(uint32_t* r, uint32_t addr) {
    asm volatile("ldmatrix.sync.aligned.m8n8.x4.shared.b16 {%0,%1,%2,%3}, [%4];"
                 : "=r"(r[0]), "=r"(r[1]), "=r"(r[2]), "=r"(r[3]) : "r"(addr));
}
__device__ __forceinline__ void mma_fp16(float* d, const uint32_t* a,
                                         const uint32_t* b) {
    asm volatile(
        "mma.sync.aligned.m16n8k16.row.col.f32.f16.f16.f32 "
        "{%0,%1,%2,%3}, {%4,%5,%6,%7}, {%8,%9}, {%0,%1,%2,%3};"
        : "+f"(d[0]), "+f"(d[1]), "+f"(d[2]), "+f"(d[3])
        : "r"(a[0]), "r"(a[1]), "r"(a[2]), "r"(a[3]), "r"(b[0]), "r"(b[1]));
}
__device__ __forceinline__ void acc_row(float4& acc, uint2 v) {
    float2 f0 = __half22float2(*(__half2*)&v.x);
    float2 f1 = __half22float2(*(__half2*)&v.y);
    acc.x += f0.x; acc.y += f0.y; acc.z += f1.x; acc.w += f1.y;
}

// ================= CSR build + W preconvert (4 edges/thread, MLP>=8) =======
__global__ void count_convw_kernel(const int* __restrict__ ei,
                                   const float* __restrict__ fc_w,
                                   const float* __restrict__ Wl,
                                   const float* __restrict__ Wr) {
    int base = blockIdx.x * blockDim.x + threadIdx.x;   // 0..E_QUARTER-1
    int d0 = __ldg(ei + N_EDGES + base);
    int d1 = __ldg(ei + N_EDGES + base + E_QUARTER);
    int d2 = __ldg(ei + N_EDGES + base + 2 * E_QUARTER);
    int d3 = __ldg(ei + N_EDGES + base + 3 * E_QUARTER);
    atomicAdd(&g_cnt[d0], 1);
    atomicAdd(&g_cnt[d1], 1);
    atomicAdd(&g_cnt[d2], 1);
    atomicAdd(&g_cnt[d3], 1);
    if (base < 7 * D * D) {
        int t = base >> 14, e = base & (D * D - 1);
        const float* src = (t == 0) ? fc_w
                           : (t <= 3 ? Wl + (size_t)(t - 1) * D * D
                                     : Wr + (size_t)(t - 4) * D * D);
        g_w[base] = __float2half_rn(__ldg(src + e));
    }
}
__global__ __launch_bounds__(SCAN_BLK) void scan1_kernel() {
    __shared__ int sh[SCAN_BLK];
    int t = threadIdx.x;
    int i = blockIdx.x * SCAN_BLK + t;
    int v = (i < N_NODES) ? g_cnt[i] : 0;
    sh[t] = v;
    __syncthreads();
#pragma unroll
    for (int off = 1; off < SCAN_BLK; off <<= 1) {
        int x = (t >= off) ? sh[t - off] : 0;
        __syncthreads();
        sh[t] += x;
        __syncthreads();
    }
    if (i < N_NODES) g_scan[i] = sh[t];
    if (t == SCAN_BLK - 1) g_bsum[blockIdx.x] = sh[t];
}
// scan3 with block-sum scan folded in; also restore-zeros g_cnt.
__global__ void scan3_kernel() {
    __shared__ int sh[64];
    int t = threadIdx.x;
    int v = 0;
    if (t < 64) {
        v = (t < N_SCAN_BLKS) ? g_bsum[t] : 0;
        sh[t] = v;
    }
    __syncthreads();
#pragma unroll
    for (int off = 1; off < 64; off <<= 1) {
        int x = (t >= off && t < 64) ? sh[t - off] : 0;
        __syncthreads();
        if (t < 64) sh[t] += x;
        __syncthreads();
    }
    if (t < 64) sh[t] -= v;   // exclusive offsets
    __syncthreads();
    int i = blockIdx.x * blockDim.x + t;
    if (i < N_NODES) {
        g_rowptr[i + 1] = g_scan[i] + sh[i >> 10];
        g_cnt[i] = 0;          // restore-zero for next graph replay
    }
    if (i == 0) g_rowptr[0] = 0;
}
__global__ void fill_kernel(const int* __restrict__ ei) {
    int base = blockIdx.x * blockDim.x + threadIdx.x;   // 0..E_QUARTER-1
    int s[4], d[4];
#pragma unroll
    for (int j = 0; j < 4; j++) {
        s[j] = __ldg(ei + base + j * E_QUARTER);
        d[j] = __ldg(ei + N_EDGES + base + j * E_QUARTER);
    }
#pragma unroll
    for (int j = 0; j < 4; j++) {
        int pos = __ldg(&g_rowptr[d[j]]) + atomicAdd(&g_fill[d[j]], 1);
        g_col[pos] = s[j];
    }
}

// ================= gather (fp16): agg[n] = mean_{s in nbrs(n)} h[s] =================
__global__ __launch_bounds__(256) void gather_kernel(const __half* __restrict__ h,
                                                     __half* __restrict__ agg) {
    int warp = (blockIdx.x * 256 + threadIdx.x) >> 5;
    int lane = threadIdx.x & 31;
    if (warp >= N_NODES) return;
    int beg = __ldg(&g_rowptr[warp]);
    int end = __ldg(&g_rowptr[warp + 1]);
    const uint2* hp = (const uint2*)h;   // 32 uint2 per row
    float4 acc = make_float4(0.f, 0.f, 0.f, 0.f);
    int k = beg;
    for (; k + 4 <= end; k += 4) {
        int s0 = __ldg(&g_col[k]);
        int s1 = __ldg(&g_col[k + 1]);
        int s2 = __ldg(&g_col[k + 2]);
        int s3 = __ldg(&g_col[k + 3]);
        uint2 v0 = __ldg(hp + (size_t)s0 * 32 + lane);
        uint2 v1 = __ldg(hp + (size_t)s1 * 32 + lane);
        uint2 v2 = __ldg(hp + (size_t)s2 * 32 + lane);
        uint2 v3 = __ldg(hp + (size_t)s3 * 32 + lane);
        acc_row(acc, v0); acc_row(acc, v1); acc_row(acc, v2); acc_row(acc, v3);
    }
    for (; k < end; k++) {
        int s0 = __ldg(&g_col[k]);
        uint2 v0 = __ldg(hp + (size_t)s0 * 32 + lane);
        acc_row(acc, v0);
    }
    float sc = 1.0f / (float)max(end - beg, 1);
    uint2 o;
    o.x = cvt_f16x2(acc.x * sc, acc.y * sc);
    o.y = cvt_f16x2(acc.z * sc, acc.w * sc);
    ((uint2*)agg)[(size_t)warp * 32 + lane] = o;
}

// ================= mma.sync fp16 single-pass GEMM (swizzled smem) =================
// Tiles: 128 rows x 256 B, XOR-swizzled 16B chunks: off = r*256 + ((c ^ (r&7))<<4)
// MODE 0: proj   out = relu(x(fp32)@W^T + b)              -> fp16 h
// MODE 1: layer  out = relu(LN(agg@Wl^T + h@Wr^T + b))    -> fp16 h (in place)
// MODE 2: last   out = agg@Wl^T + h@Wr^T + b              -> fp32 out_node
#define TILE_B 32768                       // 128 * 256
#define OFF_A 0
#define OFF_W (OFF_A + TILE_B)
#define GEMM_SMEM (2 * TILE_B)             // 65536

template <int MODE>
__global__ __launch_bounds__(256, 2) void gemm_mma(
    const float* __restrict__ xf32,        // MODE 0 only
    const __half* __restrict__ aggbuf,     // MODE 1/2 seg0 A
    const __half* __restrict__ hbuf,       // MODE 1/2 seg1 A
    int w0idx, int w1idx,
    const float* __restrict__ bias,
    const float* __restrict__ lng, const float* __restrict__ lnb,
    void* __restrict__ out) {
    extern __shared__ __align__(16) char smem[];
    const uint32_t sb = smem_u32(smem);
    const int tid = threadIdx.x;
    const int lane = tid & 31;
    const int wid = tid >> 5;
    const int warpM = wid >> 1;
    const int warpN = wid & 1;
    const int row0 = blockIdx.x * 128;
    const int g = lane >> 2;
    const int t = lane & 3;
    constexpr int NSEG = (MODE == 0) ? 1 : 2;
    constexpr bool DO_LN = (MODE == 1);
    constexpr bool DO_RELU = (MODE <= 1);
    constexpr bool OUT_HALF = (MODE <= 1);

    // restore-zero of g_fill for next replay (proj runs right after fill_kernel)
    if (MODE == 0) {
        for (int i = blockIdx.x * 256 + tid; i < N_NODES; i += gridDim.x * 256)
            g_fill[i] = 0;
    }

    float d[2][8][4];
#pragma unroll
    for (int mt = 0; mt < 2; mt++)
#pragma unroll
        for (int nt = 0; nt < 8; nt++)
#pragma unroll
            for (int e = 0; e < 4; e++) d[mt][nt][e] = 0.f;

    const int frag = lane >> 3;
    const int rs = lane & 7;               // swizzle key (row & 7 of every frag row)
    const int fhiA = frag >> 1;            // A chunk low bit
    const int floB = frag & 1;             // B chunk low bit
    const uint32_t a_base =
        sb + OFF_A + (uint32_t)((warpM * 32 + (frag & 1) * 8 + rs) * 256);
    const uint32_t b_base =
        sb + OFF_W + (uint32_t)((warpN * 64 + (frag >> 1) * 8 + rs) * 256);

#pragma unroll
    for (int seg = 0; seg < NSEG; seg++) {
        if (seg > 0) __syncthreads();
        const int widx = (seg == 0) ? w0idx : w1idx;
        const __half* wsrc = g_w + (size_t)widx * D * D;

        // -------- fill: 128 rows x 16 chunks of 16B per tile, swizzled --------
#pragma unroll
        for (int it = 0; it < 8; it++) {
            int slot = it * 256 + tid;     // 0..2047
            int r = slot >> 4;
            int c = slot & 15;
            uint32_t off = (uint32_t)(r * 256 + ((c ^ (r & 7)) << 4));

            *(uint4*)(smem + OFF_W + off) = __ldg((const uint4*)(wsrc + r * D) + c);

            int grow = row0 + r;
            uint4 aval = make_uint4(0u, 0u, 0u, 0u);
            if (grow < N_NODES) {
                if (MODE == 0) {
                    const float4* xp =
                        (const float4*)(xf32 + (size_t)grow * D + c * 8);
                    float4 v0 = __ldg(xp);
                    float4 v1 = __ldg(xp + 1);
                    aval.x = cvt_f16x2(v0.x, v0.y);
                    aval.y = cvt_f16x2(v0.z, v0.w);
                    aval.z = cvt_f16x2(v1.x, v1.y);
                    aval.w = cvt_f16x2(v1.z, v1.w);
                } else {
                    const __half* src = (seg == 0) ? aggbuf : hbuf;
                    aval = __ldg((const uint4*)(src + (size_t)grow * D) + c);
                }
            }
            *(uint4*)(smem + OFF_A + off) = aval;
        }
        __syncthreads();

        // -------- compute: single fp16 pass --------
#pragma unroll
        for (int ks = 0; ks < 8; ks++) {
            const uint32_t swA = (uint32_t)(((2 * ks + fhiA) ^ rs) << 4);
            const uint32_t swB = (uint32_t)(((2 * ks + floB) ^ rs) << 4);
            uint32_t af[2][4];
            ldmx4(af[0], a_base + swA);
            ldmx4(af[1], a_base + 4096 + swA);   // +16 rows
            uint32_t bf[8][2];
#pragma unroll
            for (int ntp = 0; ntp < 4; ntp++) {
                uint32_t r4[4];
                ldmx4(r4, b_base + ntp * 4096 + swB);   // +16 rows per ntp
                bf[2 * ntp][0] = r4[0]; bf[2 * ntp][1] = r4[1];
                bf[2 * ntp + 1][0] = r4[2]; bf[2 * ntp + 1][1] = r4[3];
            }
#pragma unroll
            for (int mt = 0; mt < 2; mt++)
#pragma unroll
                for (int nt = 0; nt < 8; nt++)
                    mma_fp16(d[mt][nt], af[mt], bf[nt]);
        }
    }

    // ================= epilogue =================
#pragma unroll
    for (int nt = 0; nt < 8; nt++) {
        int C = warpN * 64 + nt * 8 + 2 * t;
        float2 bv = __ldg((const float2*)(bias + C));
#pragma unroll
        for (int mt = 0; mt < 2; mt++) {
            d[mt][nt][0] += bv.x; d[mt][nt][1] += bv.y;
            d[mt][nt][2] += bv.x; d[mt][nt][3] += bv.y;
        }
    }

    if (DO_LN) {
        __syncthreads();
        float* red_s = (float*)smem;        // [128][2]
        float* red_q = red_s + 256;
        float* s_mu = red_q + 256;
        float* s_rs = s_mu + 128;
#pragma unroll
        for (int mt = 0; mt < 2; mt++) {
#pragma unroll
            for (int rh = 0; rh < 2; rh++) {
                float s = 0.f, q = 0.f;
#pragma unroll
                for (int nt = 0; nt < 8; nt++) {
                    float v0 = d[mt][nt][2 * rh], v1 = d[mt][nt][2 * rh + 1];
                    s += v0 + v1;
                    q += v0 * v0 + v1 * v1;
                }
                s += __shfl_xor_sync(0xffffffff, s, 1);
                s += __shfl_xor_sync(0xffffffff, s, 2);
                q += __shfl_xor_sync(0xffffffff, q, 1);
                q += __shfl_xor_sync(0xffffffff, q, 2);
                if (t == 0) {
                    int r = warpM * 32 + mt * 16 + rh * 8 + g;
                    red_s[r * 2 + warpN] = s;
                    red_q[r * 2 + warpN] = q;
                }
            }
        }
        __syncthreads();
        if (tid < 128) {
            float st = red_s[tid * 2] + red_s[tid * 2 + 1];
            float qt = red_q[tid * 2] + red_q[tid * 2 + 1];
            float mu = st * (1.0f / 128.0f);
            float var = qt * (1.0f / 128.0f) - mu * mu;
            s_mu[tid] = mu;
            s_rs[tid] = rsqrtf(var + LN_EPS);
        }
        __syncthreads();
#pragma unroll
        for (int nt = 0; nt < 8; nt++) {
            int C = warpN * 64 + nt * 8 + 2 * t;
            float2 gv = __ldg((const float2*)(lng + C));
            float2 bv = __ldg((const float2*)(lnb + C));
#pragma unroll
            for (int mt = 0; mt < 2; mt++) {
#pragma unroll
                for (int rh = 0; rh < 2; rh++) {
                    int r = warpM * 32 + mt * 16 + rh * 8 + g;
                    float mu = s_mu[r], rsv = s_rs[r];
                    d[mt][nt][2 * rh] = (d[mt][nt][2 * rh] - mu) * rsv * gv.x + bv.x;
                    d[mt][nt][2 * rh + 1] =
                        (d[mt][nt][2 * rh + 1] - mu) * rsv * gv.y + bv.y;
                }
            }
        }
    }

    if (DO_RELU) {
#pragma unroll
        for (int mt = 0; mt < 2; mt++)
#pragma unroll
            for (int nt = 0; nt < 8; nt++)
#pragma unroll
                for (int e = 0; e < 4; e++) d[mt][nt][e] = fmaxf(d[mt][nt][e], 0.f);
    }

    // store
#pragma unroll
    for (int mt = 0; mt < 2; mt++) {
#pragma unroll
        for (int rh = 0; rh < 2; rh++) {
            int R = row0 + warpM * 32 + mt * 16 + rh * 8 + g;
            if (R < N_NODES) {
                if (OUT_HALF) {
                    __half* pr = (__half*)out + (size_t)R * D + warpN * 64 + 2 * t;
#pragma unroll
                    for (int nt = 0; nt < 8; nt++)
                        *(uint32_t*)(pr + nt * 8) =
                            cvt_f16x2(d[mt][nt][2 * rh], d[mt][nt][2 * rh + 1]);
                } else {
                    float* pr = (float*)out + (size_t)R * D + warpN * 64 + 2 * t;
#pragma unroll
                    for (int nt = 0; nt < 8; nt++)
                        *(float2*)(pr + nt * 8) =
                            make_float2(d[mt][nt][2 * rh], d[mt][nt][2 * rh + 1]);
                }
            }
        }
    }
}

// ---------------- per-graph sum pool (batch sorted; 4 row-chunks, no atomics) ----
__global__ __launch_bounds__(512) void graph_pool_kernel(
    const float* __restrict__ node, const int* __restrict__ batch,
    float* __restrict__ out) {
    __shared__ float red[4][128];
    int gidx = blockIdx.x;
    int c = threadIdx.x & 127;
    int chunk = threadIdx.x >> 7;   // 0..3
    int lo = 0, hi = N_NODES;
    while (lo < hi) {
        int mid = (lo + hi) >> 1;
        if (__ldg(batch + mid) < gidx) lo = mid + 1; else hi = mid;
    }
    int start = lo;
    hi = N_NODES;
    while (lo < hi) {
        int mid = (lo + hi) >> 1;
        if (__ldg(batch + mid) < gidx + 1) lo = mid + 1; else hi = mid;
    }
    int end = lo;
    float acc = 0.f;
    int n = start + chunk;
    for (; n + 12 < end; n += 16) {
        acc += __ldg(node + (size_t)(n + 0) * D + c);
        acc += __ldg(node + (size_t)(n + 4) * D + c);
        acc += __ldg(node + (size_t)(n + 8) * D + c);
        acc += __ldg(node + (size_t)(n + 12) * D + c);
    }
    for (; n < end; n += 4) acc += __ldg(node + (size_t)n * D + c);
    red[chunk][c] = acc;
    __syncthreads();
    if (chunk == 0)
        out[(size_t)gidx * D + c] =
            (red[0][c] + red[1][c]) + (red[2][c] + red[3][c]);
}

// ---------------- launch ----------------
extern "C" void kernel_launch(void* const* d_in, const int* in_sizes, int n_in,
                              void* d_out, int out_size) {
    const float* x = (const float*)d_in[0];
    const int* ei = (const int*)d_in[1];
    const int* batch = (const int*)d_in[2];
    const float* fc_w = (const float*)d_in[3];
    const float* fc_b = (const float*)d_in[4];
    const float* Wl = (const float*)d_in[5];
    const float* bl = (const float*)d_in[6];
    const float* Wr = (const float*)d_in[7];
    const float* lng = (const float*)d_in[8];
    const float* lnb = (const float*)d_in[9];

    float* out_node = (float*)d_out;
    float* out_graph = out_node + (size_t)N_NODES * D;

    __half *h, *agg;
    cudaGetSymbolAddress((void**)&h, g_h);
    cudaGetSymbolAddress((void**)&agg, g_agg);

    cudaFuncSetAttribute(gemm_mma<0>,
                         cudaFuncAttributeMaxDynamicSharedMemorySize, GEMM_SMEM);
    cudaFuncSetAttribute(gemm_mma<1>,
                         cudaFuncAttributeMaxDynamicSharedMemorySize, GEMM_SMEM);
    cudaFuncSetAttribute(gemm_mma<2>,
                         cudaFuncAttributeMaxDynamicSharedMemorySize, GEMM_SMEM);

    // CSR build (4 edges/thread; W preconvert folded into count)
    count_convw_kernel<<<(E_QUARTER + 255) / 256, 256>>>(ei, fc_w, Wl, Wr);
    scan1_kernel<<<N_SCAN_BLKS, SCAN_BLK>>>();
    scan3_kernel<<<(N_NODES + 255) / 256, 256>>>();
    fill_kernel<<<(E_QUARTER + 255) / 256, 256>>>(ei);

    const int GBLK = (N_NODES + 127) / 128;  // 313

    // input projection + ReLU -> h (fp16); also restore-zeros g_fill
    gemm_mma<0><<<GBLK, 256, GEMM_SMEM>>>(
        x, nullptr, nullptr, 0, 0, fc_b, nullptr, nullptr, h);

    for (int i = 0; i < 3; i++) {
        gather_kernel<<<(N_NODES * 32 + 255) / 256, 256>>>(h, agg);
        if (i < 2) {
            gemm_mma<1><<<GBLK, 256, GEMM_SMEM>>>(
                nullptr, agg, h, 1 + i, 4 + i,
                bl + i * D, lng + i * D, lnb + i * D, h);
        } else {
            gemm_mma<2><<<GBLK, 256, GEMM_SMEM>>>(
                nullptr, agg, h, 1 + i, 4 + i,
                bl + i * D, nullptr, nullptr, out_node);
        }
    }

    graph_pool_kernel<<<N_GRAPHS, 512>>>(out_node, batch, out_graph);
}

// round 14
// speedup vs baseline: 1.0235x; 1.0235x over previous
#include <cuda_runtime.h>
#include <cuda_fp16.h>
#include <cstdint>

#define N_NODES 40000
#define N_EDGES 640000
#define N_GRAPHS 64
#define D 128
#define LN_EPS 1e-5f
#define SCAN_BLK 1024
#define N_SCAN_BLKS ((N_NODES + SCAN_BLK - 1) / SCAN_BLK)   // 40
#define E_QUARTER (N_EDGES / 4)                             // 160000

// ---------------- scratch (no allocations allowed) ----------------
__device__ __half g_h[(size_t)N_NODES * D];
__device__ __half g_agg[(size_t)N_NODES * D];
__device__ __half g_w[7 * D * D];     // 0: fc_w, 1-3: Wl, 4-6: Wr (fp16)
__device__ int g_cnt[N_NODES];
__device__ int g_scan[N_NODES];
__device__ int g_bsum[N_SCAN_BLKS];
__device__ int g_rowptr[N_NODES + 1];
__device__ int g_col[N_EDGES];

// ================= helpers =================
__device__ __forceinline__ uint32_t smem_u32(const void* p) {
    uint32_t a;
    asm("{ .reg .u64 t; cvta.to.shared.u64 t, %1; cvt.u32.u64 %0, t; }"
        : "=r"(a) : "l"(p));
    return a;
}
// pack (lo, hi) floats -> f16x2 (lo in low half)
__device__ __forceinline__ uint32_t cvt_f16x2(float lo, float hi) {
    uint32_t r;
    asm("cvt.rn.f16x2.f32 %0, %1, %2;" : "=r"(r) : "f"(hi), "f"(lo));
    return r;
}
__device__ __forceinline__ void ldmx4(uint32_t* r, uint32_t addr) {
    asm volatile("ldmatrix.sync.aligned.m8n8.x4.shared.b16 {%0,%1,%2,%3}, [%4];"
                 : "=r"(r[0]), "=r"(r[1]), "=r"(r[2]), "=r"(r[3]) : "r"(addr));
}
__device__ __forceinline__ void mma_fp16(float* d, const uint32_t* a,
                                         const uint32_t* b) {
    asm volatile(
        "mma.sync.aligned.m16n8k16.row.col.f32.f16.f16.f32 "
        "{%0,%1,%2,%3}, {%4,%5,%6,%7}, {%8,%9}, {%0,%1,%2,%3};"
        : "+f"(d[0]), "+f"(d[1]), "+f"(d[2]), "+f"(d[3])
        : "r"(a[0]), "r"(a[1]), "r"(a[2]), "r"(a[3]), "r"(b[0]), "r"(b[1]));
}
__device__ __forceinline__ void acc_row(float4& acc, uint2 v) {
    float2 f0 = __half22float2(*(__half2*)&v.x);
    float2 f1 = __half22float2(*(__half2*)&v.y);
    acc.x += f0.x; acc.y += f0.y; acc.z += f1.x; acc.w += f1.y;
}

// ================= W preconvert (main branch) =================
__global__ void convw_kernel(const float* __restrict__ fc_w,
                             const float* __restrict__ Wl,
                             const float* __restrict__ Wr) {
    int i = blockIdx.x * blockDim.x + threadIdx.x;
    if (i < 7 * D * D) {
        int t = i >> 14, e = i & (D * D - 1);
        const float* src = (t == 0) ? fc_w
                           : (t <= 3 ? Wl + (size_t)(t - 1) * D * D
                                     : Wr + (size_t)(t - 4) * D * D);
        g_w[i] = __float2half_rn(__ldg(src + e));
    }
}

// ================= CSR build (side branch) =================
__global__ void count_kernel(const int* __restrict__ ei) {
    int base = blockIdx.x * blockDim.x + threadIdx.x;   // 0..E_QUARTER-1
    int d0 = __ldg(ei + N_EDGES + base);
    int d1 = __ldg(ei + N_EDGES + base + E_QUARTER);
    int d2 = __ldg(ei + N_EDGES + base + 2 * E_QUARTER);
    int d3 = __ldg(ei + N_EDGES + base + 3 * E_QUARTER);
    atomicAdd(&g_cnt[d0], 1);
    atomicAdd(&g_cnt[d1], 1);
    atomicAdd(&g_cnt[d2], 1);
    atomicAdd(&g_cnt[d3], 1);
}
__global__ __launch_bounds__(SCAN_BLK) void scan1_kernel() {
    __shared__ int sh[SCAN_BLK];
    int t = threadIdx.x;
    int i = blockIdx.x * SCAN_BLK + t;
    int v = (i < N_NODES) ? g_cnt[i] : 0;
    sh[t] = v;
    __syncthreads();
#pragma unroll
    for (int off = 1; off < SCAN_BLK; off <<= 1) {
        int x = (t >= off) ? sh[t - off] : 0;
        __syncthreads();
        sh[t] += x;
        __syncthreads();
    }
    if (i < N_NODES) g_scan[i] = sh[t];
    if (t == SCAN_BLK - 1) g_bsum[blockIdx.x] = sh[t];
}
// scan3 with block-sum scan folded in; also restore-zeros g_cnt.
__global__ void scan3_kernel() {
    __shared__ int sh[64];
    int t = threadIdx.x;
    int v = 0;
    if (t < 64) {
        v = (t < N_SCAN_BLKS) ? g_bsum[t] : 0;
        sh[t] = v;
    }
    __syncthreads();
#pragma unroll
    for (int off = 1; off < 64; off <<= 1) {
        int x = (t >= off && t < 64) ? sh[t - off] : 0;
        __syncthreads();
        if (t < 64) sh[t] += x;
        __syncthreads();
    }
    if (t < 64) sh[t] -= v;   // exclusive offsets
    __syncthreads();
    int i = blockIdx.x * blockDim.x + t;
    if (i < N_NODES) {
        g_rowptr[i + 1] = g_scan[i] + sh[i >> 10];
        g_cnt[i] = 0;          // restore-zero for next graph replay
    }
    if (i == 0) g_rowptr[0] = 0;
}
// fill: pos = atomicAdd(&rowptr[d], 1). Post-fill rowptr[d] = original rowptr[d+1].
__global__ void fill_kernel(const int* __restrict__ ei) {
    int base = blockIdx.x * blockDim.x + threadIdx.x;   // 0..E_QUARTER-1
    int s[4], d[4];
#pragma unroll
    for (int j = 0; j < 4; j++) {
        s[j] = __ldg(ei + base + j * E_QUARTER);
        d[j] = __ldg(ei + N_EDGES + base + j * E_QUARTER);
    }
#pragma unroll
    for (int j = 0; j < 4; j++) {
        int pos = atomicAdd(&g_rowptr[d[j]], 1);
        g_col[pos] = s[j];
    }
}

// ================= gather (fp16): agg[n] = mean_{s in nbrs(n)} h[s] ==========
// post-fill rowptr semantics: beg = rowptr[n-1] (0 for n=0), end = rowptr[n].
__global__ __launch_bounds__(256) void gather_kernel(const __half* __restrict__ h,
                                                     __half* __restrict__ agg) {
    int warp = (blockIdx.x * 256 + threadIdx.x) >> 5;
    int lane = threadIdx.x & 31;
    if (warp >= N_NODES) return;
    int beg = (warp > 0) ? __ldg(&g_rowptr[warp - 1]) : 0;
    int end = __ldg(&g_rowptr[warp]);
    const uint2* hp = (const uint2*)h;   // 32 uint2 per row
    float4 acc = make_float4(0.f, 0.f, 0.f, 0.f);
    int k = beg;
    for (; k + 4 <= end; k += 4) {
        int s0 = __ldg(&g_col[k]);
        int s1 = __ldg(&g_col[k + 1]);
        int s2 = __ldg(&g_col[k + 2]);
        int s3 = __ldg(&g_col[k + 3]);
        uint2 v0 = __ldg(hp + (size_t)s0 * 32 + lane);
        uint2 v1 = __ldg(hp + (size_t)s1 * 32 + lane);
        uint2 v2 = __ldg(hp + (size_t)s2 * 32 + lane);
        uint2 v3 = __ldg(hp + (size_t)s3 * 32 + lane);
        acc_row(acc, v0); acc_row(acc, v1); acc_row(acc, v2); acc_row(acc, v3);
    }
    for (; k < end; k++) {
        int s0 = __ldg(&g_col[k]);
        uint2 v0 = __ldg(hp + (size_t)s0 * 32 + lane);
        acc_row(acc, v0);
    }
    float sc = 1.0f / (float)max(end - beg, 1);
    uint2 o;
    o.x = cvt_f16x2(acc.x * sc, acc.y * sc);
    o.y = cvt_f16x2(acc.z * sc, acc.w * sc);
    ((uint2*)agg)[(size_t)warp * 32 + lane] = o;
}

// ================= mma.sync fp16 single-pass GEMM (swizzled smem) =================
// Tiles: 128 rows x 256 B, XOR-swizzled 16B chunks: off = r*256 + ((c ^ (r&7))<<4)
// MODE 0: proj   out = relu(x(fp32)@W^T + b)              -> fp16 h
// MODE 1: layer  out = relu(LN(agg@Wl^T + h@Wr^T + b))    -> fp16 h (in place)
// MODE 2: last   out = agg@Wl^T + h@Wr^T + b              -> fp32 out_node
#define TILE_B 32768                       // 128 * 256
#define OFF_A 0
#define OFF_W (OFF_A + TILE_B)
#define GEMM_SMEM (2 * TILE_B)             // 65536

template <int MODE>
__global__ __launch_bounds__(256, 2) void gemm_mma(
    const float* __restrict__ xf32,        // MODE 0 only
    const __half* __restrict__ aggbuf,     // MODE 1/2 seg0 A
    const __half* __restrict__ hbuf,       // MODE 1/2 seg1 A
    int w0idx, int w1idx,
    const float* __restrict__ bias,
    const float* __restrict__ lng, const float* __restrict__ lnb,
    void* __restrict__ out) {
    extern __shared__ __align__(16) char smem[];
    const uint32_t sb = smem_u32(smem);
    const int tid = threadIdx.x;
    const int lane = tid & 31;
    const int wid = tid >> 5;
    const int warpM = wid >> 1;
    const int warpN = wid & 1;
    const int row0 = blockIdx.x * 128;
    const int g = lane >> 2;
    const int t = lane & 3;
    constexpr int NSEG = (MODE == 0) ? 1 : 2;
    constexpr bool DO_LN = (MODE == 1);
    constexpr bool DO_RELU = (MODE <= 1);
    constexpr bool OUT_HALF = (MODE <= 1);

    float d[2][8][4];
#pragma unroll
    for (int mt = 0; mt < 2; mt++)
#pragma unroll
        for (int nt = 0; nt < 8; nt++)
#pragma unroll
            for (int e = 0; e < 4; e++) d[mt][nt][e] = 0.f;

    const int frag = lane >> 3;
    const int rs = lane & 7;               // swizzle key (row & 7 of every frag row)
    const int fhiA = frag >> 1;            // A chunk low bit
    const int floB = frag & 1;             // B chunk low bit
    const uint32_t a_base =
        sb + OFF_A + (uint32_t)((warpM * 32 + (frag & 1) * 8 + rs) * 256);
    const uint32_t b_base =
        sb + OFF_W + (uint32_t)((warpN * 64 + (frag >> 1) * 8 + rs) * 256);

#pragma unroll
    for (int seg = 0; seg < NSEG; seg++) {
        if (seg > 0) __syncthreads();
        const int widx = (seg == 0) ? w0idx : w1idx;
        const __half* wsrc = g_w + (size_t)widx * D * D;

        // -------- fill: 128 rows x 16 chunks of 16B per tile, swizzled --------
#pragma unroll
        for (int it = 0; it < 8; it++) {
            int slot = it * 256 + tid;     // 0..2047
            int r = slot >> 4;
            int c = slot & 15;
            uint32_t off = (uint32_t)(r * 256 + ((c ^ (r & 7)) << 4));

            *(uint4*)(smem + OFF_W + off) = __ldg((const uint4*)(wsrc + r * D) + c);

            int grow = row0 + r;
            uint4 aval = make_uint4(0u, 0u, 0u, 0u);
            if (grow < N_NODES) {
                if (MODE == 0) {
                    const float4* xp =
                        (const float4*)(xf32 + (size_t)grow * D + c * 8);
                    float4 v0 = __ldg(xp);
                    float4 v1 = __ldg(xp + 1);
                    aval.x = cvt_f16x2(v0.x, v0.y);
                    aval.y = cvt_f16x2(v0.z, v0.w);
                    aval.z = cvt_f16x2(v1.x, v1.y);
                    aval.w = cvt_f16x2(v1.z, v1.w);
                } else {
                    const __half* src = (seg == 0) ? aggbuf : hbuf;
                    aval = __ldg((const uint4*)(src + (size_t)grow * D) + c);
                }
            }
            *(uint4*)(smem + OFF_A + off) = aval;
        }
        __syncthreads();

        // -------- compute: single fp16 pass --------
#pragma unroll
        for (int ks = 0; ks < 8; ks++) {
            const uint32_t swA = (uint32_t)(((2 * ks + fhiA) ^ rs) << 4);
            const uint32_t swB = (uint32_t)(((2 * ks + floB) ^ rs) << 4);
            uint32_t af[2][4];
            ldmx4(af[0], a_base + swA);
            ldmx4(af[1], a_base + 4096 + swA);   // +16 rows
            uint32_t bf[8][2];
#pragma unroll
            for (int ntp = 0; ntp < 4; ntp++) {
                uint32_t r4[4];
                ldmx4(r4, b_base + ntp * 4096 + swB);   // +16 rows per ntp
                bf[2 * ntp][0] = r4[0]; bf[2 * ntp][1] = r4[1];
                bf[2 * ntp + 1][0] = r4[2]; bf[2 * ntp + 1][1] = r4[3];
            }
#pragma unroll
            for (int mt = 0; mt < 2; mt++)
#pragma unroll
                for (int nt = 0; nt < 8; nt++)
                    mma_fp16(d[mt][nt], af[mt], bf[nt]);
        }
    }

    // ================= epilogue =================
#pragma unroll
    for (int nt = 0; nt < 8; nt++) {
        int C = warpN * 64 + nt * 8 + 2 * t;
        float2 bv = __ldg((const float2*)(bias + C));
#pragma unroll
        for (int mt = 0; mt < 2; mt++) {
            d[mt][nt][0] += bv.x; d[mt][nt][1] += bv.y;
            d[mt][nt][2] += bv.x; d[mt][nt][3] += bv.y;
        }
    }

    if (DO_LN) {
        __syncthreads();
        float* red_s = (float*)smem;        // [128][2]
        float* red_q = red_s + 256;
        float* s_mu = red_q + 256;
        float* s_rs = s_mu + 128;
#pragma unroll
        for (int mt = 0; mt < 2; mt++) {
#pragma unroll
            for (int rh = 0; rh < 2; rh++) {
                float s = 0.f, q = 0.f;
#pragma unroll
                for (int nt = 0; nt < 8; nt++) {
                    float v0 = d[mt][nt][2 * rh], v1 = d[mt][nt][2 * rh + 1];
                    s += v0 + v1;
                    q += v0 * v0 + v1 * v1;
                }
                s += __shfl_xor_sync(0xffffffff, s, 1);
                s += __shfl_xor_sync(0xffffffff, s, 2);
                q += __shfl_xor_sync(0xffffffff, q, 1);
                q += __shfl_xor_sync(0xffffffff, q, 2);
                if (t == 0) {
                    int r = warpM * 32 + mt * 16 + rh * 8 + g;
                    red_s[r * 2 + warpN] = s;
                    red_q[r * 2 + warpN] = q;
                }
            }
        }
        __syncthreads();
        if (tid < 128) {
            float st = red_s[tid * 2] + red_s[tid * 2 + 1];
            float qt = red_q[tid * 2] + red_q[tid * 2 + 1];
            float mu = st * (1.0f / 128.0f);
            float var = qt * (1.0f / 128.0f) - mu * mu;
            s_mu[tid] = mu;
            s_rs[tid] = rsqrtf(var + LN_EPS);
        }
        __syncthreads();
#pragma unroll
        for (int nt = 0; nt < 8; nt++) {
            int C = warpN * 64 + nt * 8 + 2 * t;
            float2 gv = __ldg((const float2*)(lng + C));
            float2 bv = __ldg((const float2*)(lnb + C));
#pragma unroll
            for (int mt = 0; mt < 2; mt++) {
#pragma unroll
                for (int rh = 0; rh < 2; rh++) {
                    int r = warpM * 32 + mt * 16 + rh * 8 + g;
                    float mu = s_mu[r], rsv = s_rs[r];
                    d[mt][nt][2 * rh] = (d[mt][nt][2 * rh] - mu) * rsv * gv.x + bv.x;
                    d[mt][nt][2 * rh + 1] =
                        (d[mt][nt][2 * rh + 1] - mu) * rsv * gv.y + bv.y;
                }
            }
        }
    }

    if (DO_RELU) {
#pragma unroll
        for (int mt = 0; mt < 2; mt++)
#pragma unroll
            for (int nt = 0; nt < 8; nt++)
#pragma unroll
                for (int e = 0; e < 4; e++) d[mt][nt][e] = fmaxf(d[mt][nt][e], 0.f);
    }

    // store
#pragma unroll
    for (int mt = 0; mt < 2; mt++) {
#pragma unroll
        for (int rh = 0; rh < 2; rh++) {
            int R = row0 + warpM * 32 + mt * 16 + rh * 8 + g;
            if (R < N_NODES) {
                if (OUT_HALF) {
                    __half* pr = (__half*)out + (size_t)R * D + warpN * 64 + 2 * t;
#pragma unroll
                    for (int nt = 0; nt < 8; nt++)
                        *(uint32_t*)(pr + nt * 8) =
                            cvt_f16x2(d[mt][nt][2 * rh], d[mt][nt][2 * rh + 1]);
                } else {
                    float* pr = (float*)out + (size_t)R * D + warpN * 64 + 2 * t;
#pragma unroll
                    for (int nt = 0; nt < 8; nt++)
                        *(float2*)(pr + nt * 8) =
                            make_float2(d[mt][nt][2 * rh], d[mt][nt][2 * rh + 1]);
                }
            }
        }
    }
}

// ---------------- per-graph sum pool (batch sorted; 4 row-chunks, no atomics) ----
__global__ __launch_bounds__(512) void graph_pool_kernel(
    const float* __restrict__ node, const int* __restrict__ batch,
    float* __restrict__ out) {
    __shared__ float red[4][128];
    int gidx = blockIdx.x;
    int c = threadIdx.x & 127;
    int chunk = threadIdx.x >> 7;   // 0..3
    int lo = 0, hi = N_NODES;
    while (lo < hi) {
        int mid = (lo + hi) >> 1;
        if (__ldg(batch + mid) < gidx) lo = mid + 1; else hi = mid;
    }
    int start = lo;
    hi = N_NODES;
    while (lo < hi) {
        int mid = (lo + hi) >> 1;
        if (__ldg(batch + mid) < gidx + 1) lo = mid + 1; else hi = mid;
    }
    int end = lo;
    float acc = 0.f;
    int n = start + chunk;
    for (; n + 12 < end; n += 16) {
        acc += __ldg(node + (size_t)(n + 0) * D + c);
        acc += __ldg(node + (size_t)(n + 4) * D + c);
        acc += __ldg(node + (size_t)(n + 8) * D + c);
        acc += __ldg(node + (size_t)(n + 12) * D + c);
    }
    for (; n < end; n += 4) acc += __ldg(node + (size_t)n * D + c);
    red[chunk][c] = acc;
    __syncthreads();
    if (chunk == 0)
        out[(size_t)gidx * D + c] =
            (red[0][c] + red[1][c]) + (red[2][c] + red[3][c]);
}

// ---------------- launch ----------------
extern "C" void kernel_launch(void* const* d_in, const int* in_sizes, int n_in,
                              void* d_out, int out_size) {
    const float* x = (const float*)d_in[0];
    const int* ei = (const int*)d_in[1];
    const int* batch = (const int*)d_in[2];
    const float* fc_w = (const float*)d_in[3];
    const float* fc_b = (const float*)d_in[4];
    const float* Wl = (const float*)d_in[5];
    const float* bl = (const float*)d_in[6];
    const float* Wr = (const float*)d_in[7];
    const float* lng = (const float*)d_in[8];
    const float* lnb = (const float*)d_in[9];

    float* out_node = (float*)d_out;
    float* out_graph = out_node + (size_t)N_NODES * D;

    __half *h, *agg;
    cudaGetSymbolAddress((void**)&h, g_h);
    cudaGetSymbolAddress((void**)&agg, g_agg);

    cudaFuncSetAttribute(gemm_mma<0>,
                         cudaFuncAttributeMaxDynamicSharedMemorySize, GEMM_SMEM);
    cudaFuncSetAttribute(gemm_mma<1>,
                         cudaFuncAttributeMaxDynamicSharedMemorySize, GEMM_SMEM);
    cudaFuncSetAttribute(gemm_mma<2>,
                         cudaFuncAttributeMaxDynamicSharedMemorySize, GEMM_SMEM);

    // side stream + events created once (host-side objects, no device memory)
    static cudaStream_t s_side = nullptr;
    static cudaEvent_t s_fork = nullptr, s_join = nullptr;
    if (s_side == nullptr) {
        cudaStreamCreateWithFlags(&s_side, cudaStreamNonBlocking);
        cudaEventCreateWithFlags(&s_fork, cudaEventDisableTiming);
        cudaEventCreateWithFlags(&s_join, cudaEventDisableTiming);
    }

    const int GBLK = (N_NODES + 127) / 128;  // 313

    // ---- fork: CSR build on side stream, convW+proj on main stream ----
    cudaEventRecord(s_fork, 0);
    cudaStreamWaitEvent(s_side, s_fork, 0);

    count_kernel<<<(E_QUARTER + 255) / 256, 256, 0, s_side>>>(ei);
    scan1_kernel<<<N_SCAN_BLKS, SCAN_BLK, 0, s_side>>>();
    scan3_kernel<<<(N_NODES + 255) / 256, 256, 0, s_side>>>();
    fill_kernel<<<(E_QUARTER + 255) / 256, 256, 0, s_side>>>(ei);
    cudaEventRecord(s_join, s_side);

    convw_kernel<<<(7 * D * D + 255) / 256, 256>>>(fc_w, Wl, Wr);
    gemm_mma<0><<<GBLK, 256, GEMM_SMEM>>>(
        x, nullptr, nullptr, 0, 0, fc_b, nullptr, nullptr, h);

    cudaStreamWaitEvent(0, s_join, 0);   // join before first gather

    for (int i = 0; i < 3; i++) {
        gather_kernel<<<(N_NODES * 32 + 255) / 256, 256>>>(h, agg);
        if (i < 2) {
            gemm_mma<1><<<GBLK, 256, GEMM_SMEM>>>(
                nullptr, agg, h, 1 + i, 4 + i,
                bl + i * D, lng + i * D, lnb + i * D, h);
        } else {
            gemm_mma<2><<<GBLK, 256, GEMM_SMEM>>>(
                nullptr, agg, h, 1 + i, 4 + i,
                bl + i * D, nullptr, nullptr, out_node);
        }
    }

    graph_pool_kernel<<<N_GRAPHS, 512>>>(out_node, batch, out_graph);
}